// round 4
// baseline (speedup 1.0000x reference)
#include <cuda_runtime.h>
#include <cstdint>
#include <cstddef>

// Problem constants
#define B_  8
#define N_  2048
#define DE  1024
#define DR  512

// GEMM tiling
#define BM 128
#define BN 64
#define BK 16

// -------------------- scratch (device globals: allocation-guard safe) -----
static __device__ __align__(128) float g_q[(size_t)B_ * N_ * DR];
static __device__ __align__(128) float g_k[(size_t)B_ * N_ * DR];
static __device__ __align__(128) float g_v[(size_t)B_ * N_ * DR];
static __device__ __align__(128) float g_s[(size_t)B_ * N_ * N_];

// -------------------- helpers --------------------------------------------
__device__ __forceinline__ uint32_t f2tf(float x) {
    uint32_t u;
    asm("cvt.rna.tf32.f32 %0, %1;" : "=r"(u) : "f"(x));
    return u;
}

__device__ __forceinline__ void mma_tf32(float* c, const uint32_t* a, const uint32_t* b) {
    asm volatile(
        "mma.sync.aligned.m16n8k8.row.col.f32.tf32.tf32.f32 "
        "{%0,%1,%2,%3},{%4,%5,%6,%7},{%8,%9},{%0,%1,%2,%3};"
        : "+f"(c[0]), "+f"(c[1]), "+f"(c[2]), "+f"(c[3])
        : "r"(a[0]), "r"(a[1]), "r"(a[2]), "r"(a[3]), "r"(b[0]), "r"(b[1]));
}

// fast exp via degree-6 Taylor of 2^f (rel err ~2e-5), FFMA-pipe only
__device__ __forceinline__ float fast_exp(float x) {
    float t = x * 1.4426950408889634f;   // log2(e)
    t = fmaxf(t, -126.0f);
    float fi = floorf(t);
    float f = t - fi;
    const float c1 = 0.6931471805599453f;
    const float c2 = 0.24022650695910072f;
    const float c3 = 0.05550410866482158f;
    const float c4 = 0.009618129107628477f;
    const float c5 = 0.0013333558146428443f;
    const float c6 = 0.00015403530393381608f;
    float p = fmaf(c6, f, c5);
    p = fmaf(p, f, c4);
    p = fmaf(p, f, c3);
    p = fmaf(p, f, c2);
    p = fmaf(p, f, c1);
    p = fmaf(p, f, 1.0f);
    int e = (int)fi;                      // e in [-126, 0]
    float s = __int_as_float((uint32_t)(e + 127) << 23);
    return p * s;
}

// -------------------- GEMM core -------------------------------------------
// C[M,N] += A[M,K] * B
//   BTRANS=true : B is [N,K], K-contiguous (ldb = K)   -> used for Q*K^T
//   BTRANS=false: B is [K,N], N-contiguous (ldb = N)   -> used for X*W, P*V
// Block tile 128x64, BK=16, 256 threads (8 warps, 4x2 warp grid, 32x32 warp tile)
template <bool BTRANS>
__device__ __forceinline__ void gemm_core(
    const float* __restrict__ A, const float* __restrict__ B,
    int lda, int ldb, int ktiles, int m0, int n0,
    float (&acc)[2][4][4])
{
    __shared__ uint32_t As[2][BK][BM + 4];
    __shared__ uint32_t Bs[2][BK][BN + 4];

    const int tid  = threadIdx.x;
    const int lane = tid & 31;
    const int warp = tid >> 5;
    const int wm = (warp & 3) * 32;
    const int wn = (warp >> 2) * 32;

    // A loader: 128x16 tile, 2 float4 per thread
    const int ar = tid >> 2;              // 0..63
    const int ac = (tid & 3) << 2;        // 0,4,8,12
    const float* pa0 = A + (size_t)(m0 + ar) * lda + ac;
    const float* pa1 = pa0 + (size_t)64 * lda;

    float4 aR0, aR1, bR;

    // prologue: tile 0 -> regs
    aR0 = *(const float4*)pa0;
    aR1 = *(const float4*)pa1;
    if (BTRANS) {
        bR = *(const float4*)(B + (size_t)(n0 + (tid >> 2)) * ldb + ((tid & 3) << 2));
    } else {
        bR = *(const float4*)(B + (size_t)(tid >> 4) * ldb + n0 + ((tid & 15) << 2));
    }

    for (int t = 0; t < ktiles; ++t) {
        const int buf = t & 1;
        // regs -> shared (tf32 convert), transposed for A (and for B if BTRANS)
        As[buf][ac + 0][ar]      = f2tf(aR0.x);
        As[buf][ac + 1][ar]      = f2tf(aR0.y);
        As[buf][ac + 2][ar]      = f2tf(aR0.z);
        As[buf][ac + 3][ar]      = f2tf(aR0.w);
        As[buf][ac + 0][ar + 64] = f2tf(aR1.x);
        As[buf][ac + 1][ar + 64] = f2tf(aR1.y);
        As[buf][ac + 2][ar + 64] = f2tf(aR1.z);
        As[buf][ac + 3][ar + 64] = f2tf(aR1.w);
        if (BTRANS) {
            const int kc = (tid & 3) << 2, nr = tid >> 2;
            Bs[buf][kc + 0][nr] = f2tf(bR.x);
            Bs[buf][kc + 1][nr] = f2tf(bR.y);
            Bs[buf][kc + 2][nr] = f2tf(bR.z);
            Bs[buf][kc + 3][nr] = f2tf(bR.w);
        } else {
            const int brow = tid >> 4, bc = (tid & 15) << 2;
            Bs[buf][brow][bc + 0] = f2tf(bR.x);
            Bs[buf][brow][bc + 1] = f2tf(bR.y);
            Bs[buf][brow][bc + 2] = f2tf(bR.z);
            Bs[buf][brow][bc + 3] = f2tf(bR.w);
        }
        __syncthreads();

        // prefetch next tile while computing
        if (t + 1 < ktiles) {
            const int k0 = (t + 1) * BK;
            aR0 = *(const float4*)(pa0 + k0);
            aR1 = *(const float4*)(pa1 + k0);
            if (BTRANS)
                bR = *(const float4*)(B + (size_t)(n0 + (tid >> 2)) * ldb + k0 + ((tid & 3) << 2));
            else
                bR = *(const float4*)(B + (size_t)(k0 + (tid >> 4)) * ldb + n0 + ((tid & 15) << 2));
        }

        // compute 2 k-steps of 8
        #pragma unroll
        for (int ks = 0; ks < BK; ks += 8) {
            const int kr = ks + (lane & 3);
            const int mr = lane >> 2;
            uint32_t af[2][4], bf[4][2];
            #pragma unroll
            for (int mf = 0; mf < 2; ++mf) {
                const int m = wm + mf * 16 + mr;
                af[mf][0] = As[buf][kr][m];
                af[mf][1] = As[buf][kr][m + 8];
                af[mf][2] = As[buf][kr + 4][m];
                af[mf][3] = As[buf][kr + 4][m + 8];
            }
            #pragma unroll
            for (int nf = 0; nf < 4; ++nf) {
                const int n = wn + nf * 8 + mr;
                bf[nf][0] = Bs[buf][kr][n];
                bf[nf][1] = Bs[buf][kr + 4][n];
            }
            #pragma unroll
            for (int mf = 0; mf < 2; ++mf)
                #pragma unroll
                for (int nf = 0; nf < 4; ++nf)
                    mma_tf32(acc[mf][nf], af[mf], bf[nf]);
        }
    }
}

// -------------------- kernel 1: projections -------------------------------
// z=0: q = (x0 @ Wq + bq) * 1/sqrt(512) ; z=1: k = x1 @ Wk + bk ; z=2: v = x2 @ Wk + bk
__global__ void __launch_bounds__(256) proj_kernel(
    const float* __restrict__ x0, const float* __restrict__ x1, const float* __restrict__ x2,
    const float* __restrict__ Wq, const float* __restrict__ bq,
    const float* __restrict__ Wk, const float* __restrict__ bk)
{
    const int z = blockIdx.z;
    const float* X    = (z == 0) ? x0 : ((z == 1) ? x1 : x2);
    const float* W    = (z == 0) ? Wq : Wk;
    const float* bias = (z == 0) ? bq : bk;
    float* O          = (z == 0) ? g_q : ((z == 1) ? g_k : g_v);
    const float scale = (z == 0) ? 0.04419417382415922f : 1.0f;  // 1/sqrt(512)

    const int m0 = blockIdx.y * BM;      // M = B_*N_ = 16384
    const int n0 = blockIdx.x * BN;      // N = 512

    float acc[2][4][4];
    #pragma unroll
    for (int i = 0; i < 2; ++i)
        #pragma unroll
        for (int j = 0; j < 4; ++j)
            #pragma unroll
            for (int l = 0; l < 4; ++l) acc[i][j][l] = 0.0f;

    gemm_core<false>(X, W, DE, DR, DE / BK, m0, n0, acc);

    const int lane = threadIdx.x & 31;
    const int warp = threadIdx.x >> 5;
    const int wm = (warp & 3) * 32;
    const int wn = (warp >> 2) * 32;
    #pragma unroll
    for (int mf = 0; mf < 2; ++mf)
        #pragma unroll
        for (int nf = 0; nf < 4; ++nf) {
            const int r = m0 + wm + mf * 16 + (lane >> 2);
            const int c = n0 + wn + nf * 8 + ((lane & 3) << 1);
            const float b0 = bias[c], b1 = bias[c + 1];
            float2 v0 = make_float2((acc[mf][nf][0] + b0) * scale, (acc[mf][nf][1] + b1) * scale);
            float2 v1 = make_float2((acc[mf][nf][2] + b0) * scale, (acc[mf][nf][3] + b1) * scale);
            *(float2*)(O + (size_t)r * DR + c)       = v0;
            *(float2*)(O + (size_t)(r + 8) * DR + c) = v1;
        }
}

// -------------------- kernel 2: S = Q @ K^T (causal block skip) -----------
__global__ void __launch_bounds__(256) scores_kernel()
{
    const int b  = blockIdx.z;
    const int m0 = blockIdx.y * BM;
    const int n0 = blockIdx.x * BN;
    if (n0 > m0 + BM - 1) return;  // fully above diagonal: never read after softmax

    const float* Q  = g_q + (size_t)b * N_ * DR;
    const float* Km = g_k + (size_t)b * N_ * DR;
    float* S        = g_s + (size_t)b * N_ * N_;

    float acc[2][4][4];
    #pragma unroll
    for (int i = 0; i < 2; ++i)
        #pragma unroll
        for (int j = 0; j < 4; ++j)
            #pragma unroll
            for (int l = 0; l < 4; ++l) acc[i][j][l] = 0.0f;

    gemm_core<true>(Q, Km, DR, DR, DR / BK, m0, n0, acc);

    const int lane = threadIdx.x & 31;
    const int warp = threadIdx.x >> 5;
    const int wm = (warp & 3) * 32;
    const int wn = (warp >> 2) * 32;
    #pragma unroll
    for (int mf = 0; mf < 2; ++mf)
        #pragma unroll
        for (int nf = 0; nf < 4; ++nf) {
            const int r = m0 + wm + mf * 16 + (lane >> 2);
            const int c = n0 + wn + nf * 8 + ((lane & 3) << 1);
            *(float2*)(S + (size_t)r * N_ + c)       = make_float2(acc[mf][nf][0], acc[mf][nf][1]);
            *(float2*)(S + (size_t)(r + 8) * N_ + c) = make_float2(acc[mf][nf][2], acc[mf][nf][3]);
        }
}

// -------------------- kernel 3: causal row softmax (in-place) -------------
__device__ __forceinline__ float block_reduce_max(float v) {
    __shared__ float sm[8];
    #pragma unroll
    for (int o = 16; o > 0; o >>= 1) v = fmaxf(v, __shfl_xor_sync(0xffffffffu, v, o));
    if ((threadIdx.x & 31) == 0) sm[threadIdx.x >> 5] = v;
    __syncthreads();
    v = sm[0];
    #pragma unroll
    for (int i = 1; i < 8; ++i) v = fmaxf(v, sm[i]);
    __syncthreads();
    return v;
}

__device__ __forceinline__ float block_reduce_sum(float v) {
    __shared__ float sm2[8];
    #pragma unroll
    for (int o = 16; o > 0; o >>= 1) v += __shfl_xor_sync(0xffffffffu, v, o);
    if ((threadIdx.x & 31) == 0) sm2[threadIdx.x >> 5] = v;
    __syncthreads();
    v = sm2[0];
    #pragma unroll
    for (int i = 1; i < 8; ++i) v += sm2[i];
    __syncthreads();
    return v;
}

__global__ void __launch_bounds__(256) softmax_kernel()
{
    const int row = blockIdx.x;          // 0 .. B_*N_-1
    const int r   = row & (N_ - 1);
    float* S = g_s + (size_t)row * N_;
    const int tid = threadIdx.x;
    const int valid = r + 1;

    float v[8];
    float lmax = -3.402823466e38f;
    #pragma unroll
    for (int i = 0; i < 2; ++i) {
        const int c = (tid + i * 256) << 2;
        float4 f = *(const float4*)(S + c);
        v[i * 4 + 0] = (c + 0 < valid) ? f.x : -3.402823466e38f;
        v[i * 4 + 1] = (c + 1 < valid) ? f.y : -3.402823466e38f;
        v[i * 4 + 2] = (c + 2 < valid) ? f.z : -3.402823466e38f;
        v[i * 4 + 3] = (c + 3 < valid) ? f.w : -3.402823466e38f;
        lmax = fmaxf(lmax, fmaxf(fmaxf(v[i*4], v[i*4+1]), fmaxf(v[i*4+2], v[i*4+3])));
    }
    const float m = block_reduce_max(lmax);

    float lsum = 0.0f;
    #pragma unroll
    for (int i = 0; i < 8; ++i) {
        const int c = ((tid + (i >> 2) * 256) << 2) + (i & 3);
        float e = (c < valid) ? fast_exp(v[i] - m) : 0.0f;
        v[i] = e;
        lsum += e;
    }
    const float s = block_reduce_sum(lsum);
    const float inv = 1.0f / s;

    #pragma unroll
    for (int i = 0; i < 2; ++i) {
        const int c = (tid + i * 256) << 2;
        *(float4*)(S + c) = make_float4(v[i*4] * inv, v[i*4+1] * inv, v[i*4+2] * inv, v[i*4+3] * inv);
    }
}

// -------------------- kernel 4: out = P @ V (causal k truncation) ---------
__global__ void __launch_bounds__(256) out_kernel(float* __restrict__ out)
{
    const int b  = blockIdx.z;
    const int m0 = blockIdx.y * BM;
    const int n0 = blockIdx.x * BN;

    const float* S = g_s + (size_t)b * N_ * N_;
    const float* V = g_v + (size_t)b * N_ * DR;
    const int ktiles = (m0 + BM) / BK;   // cols > m0+BM-1 are all zero: skip

    float acc[2][4][4];
    #pragma unroll
    for (int i = 0; i < 2; ++i)
        #pragma unroll
        for (int j = 0; j < 4; ++j)
            #pragma unroll
            for (int l = 0; l < 4; ++l) acc[i][j][l] = 0.0f;

    gemm_core<false>(S, V, N_, DR, ktiles, m0, n0, acc);

    float* O = out + (size_t)b * N_ * DR;
    const int lane = threadIdx.x & 31;
    const int warp = threadIdx.x >> 5;
    const int wm = (warp & 3) * 32;
    const int wn = (warp >> 2) * 32;
    #pragma unroll
    for (int mf = 0; mf < 2; ++mf)
        #pragma unroll
        for (int nf = 0; nf < 4; ++nf) {
            const int r = m0 + wm + mf * 16 + (lane >> 2);
            const int c = n0 + wn + nf * 8 + ((lane & 3) << 1);
            *(float2*)(O + (size_t)r * DR + c)       = make_float2(acc[mf][nf][0], acc[mf][nf][1]);
            *(float2*)(O + (size_t)(r + 8) * DR + c) = make_float2(acc[mf][nf][2], acc[mf][nf][3]);
        }
}

// -------------------- launch ----------------------------------------------
extern "C" void kernel_launch(void* const* d_in, const int* in_sizes, int n_in,
                              void* d_out, int out_size)
{
    (void)in_sizes; (void)n_in; (void)out_size;
    const float* x0 = (const float*)d_in[0];
    const float* x1 = (const float*)d_in[1];
    const float* x2 = (const float*)d_in[2];
    const float* Wq = (const float*)d_in[3];
    const float* bq = (const float*)d_in[4];
    const float* Wk = (const float*)d_in[5];
    const float* bk = (const float*)d_in[6];
    float* out = (float*)d_out;

    dim3 blk(256);
    proj_kernel<<<dim3(DR / BN, (B_ * N_) / BM, 3), blk>>>(x0, x1, x2, Wq, bq, Wk, bk);
    scores_kernel<<<dim3(N_ / BN, N_ / BM, B_), blk>>>();
    softmax_kernel<<<dim3(B_ * N_), blk>>>();
    out_kernel<<<dim3(DR / BN, N_ / BM, B_), blk>>>(out);
}

// round 7
// speedup vs baseline: 1.4866x; 1.4866x over previous
#include <cuda_runtime.h>
#include <cstdint>
#include <cstddef>

// ---------------- problem constants ----------------
#define B_  8
#define N_  2048
#define DE  1024
#define DR  512

// ---------------- GEMM tiling ----------------
#define BM 128
#define BN 64
#define BK 32

// ---------------- scratch (device globals: allocation-guard safe) -----
static __device__ __align__(1024) float g_q [(size_t)B_ * N_ * DR];
static __device__ __align__(1024) float g_k [(size_t)B_ * N_ * DR];
static __device__ __align__(1024) float g_v [(size_t)B_ * N_ * DR];
static __device__ __align__(1024) float g_vt[(size_t)B_ * DR * N_];   // V^T: [b][d][t]
static __device__ __align__(1024) float g_wt[(size_t)2 * DR * DE];    // W^T: [w][n][k]
static __device__ __align__(1024) float g_s [(size_t)B_ * N_ * N_];

// ---------------- helpers ----------------
__device__ __forceinline__ uint32_t f2tf(float x) {
    uint32_t u;
    asm("cvt.rna.tf32.f32 %0, %1;" : "=r"(u) : "f"(x));
    return u;
}

__device__ __forceinline__ void mma_tf32(float* c, const uint32_t* a, const uint32_t* b) {
    asm volatile(
        "mma.sync.aligned.m16n8k8.row.col.f32.tf32.tf32.f32 "
        "{%0,%1,%2,%3},{%4,%5,%6,%7},{%8,%9},{%0,%1,%2,%3};"
        : "+f"(c[0]), "+f"(c[1]), "+f"(c[2]), "+f"(c[3])
        : "r"(a[0]), "r"(a[1]), "r"(a[2]), "r"(a[3]), "r"(b[0]), "r"(b[1]));
}

// -------------------- GEMM core -------------------------------------------
// C[M,N] (+)= A[M,K] * B^T where B is [N,K], K-contiguous rows.
// Block tile 128x64xBK32, 256 threads (8 warps, 4x2 grid of 32x32 warp tiles).
// SMEM: m-major rows of 32 tf32 (128B), SW128 XOR swizzle on 16B chunks:
//   word(m,k) = m*32 + ((k>>2) ^ (m&7))*4 + (k&3)
// -> conflict-free STS.128 fill AND conflict-free scalar LDS fragment loads.
__device__ __forceinline__ void gemm_core(
    const float* __restrict__ A, const float* __restrict__ B,
    int lda, int ldb, int ktiles, int m0, int n0,
    float (&acc)[2][4][4])
{
    __shared__ uint32_t As[2][BM * BK];   // 2 x 16 KB
    __shared__ uint32_t Bs[2][BN * BK];   // 2 x  8 KB   (total 48 KB)

    const int tid  = threadIdx.x;
    const int lane = tid & 31;
    const int warp = tid >> 5;
    const int wm = (warp & 3) * 32;
    const int wn = (warp >> 2) * 32;
    const int g = lane >> 2;        // 0..7
    const int r = lane & 3;         // 0..3

    // ---- staging: gmem pointers + swizzled store offsets ----
    const float* pAg[4];
    const float* pBg[2];
    int sA[4], sB[2];
    #pragma unroll
    for (int i = 0; i < 4; ++i) {
        const int ci = tid + 256 * i;           // 0..1023
        const int m = ci >> 3, c = ci & 7;
        pAg[i] = A + (size_t)(m0 + m) * lda + (c << 2);
        sA[i]  = m * BK + ((c ^ (m & 7)) << 2);
    }
    #pragma unroll
    for (int i = 0; i < 2; ++i) {
        const int ci = tid + 256 * i;           // 0..511
        const int m = ci >> 3, c = ci & 7;
        pBg[i] = B + (size_t)(n0 + m) * ldb + (c << 2);
        sB[i]  = m * BK + ((c ^ (m & 7)) << 2);
    }

    // ---- fragment-load address precompute (loop-invariant) ----
    int xr[8];
    #pragma unroll
    for (int cc = 0; cc < 8; ++cc) xr[cc] = ((cc ^ g) << 2);
    int pa[2][2], pb[4];
    #pragma unroll
    for (int mf = 0; mf < 2; ++mf) {
        pa[mf][0] = (wm + mf * 16 + g) * BK + r;
        pa[mf][1] = pa[mf][0] + 8 * BK;
    }
    #pragma unroll
    for (int nf = 0; nf < 4; ++nf) pb[nf] = (wn + nf * 8 + g) * BK + r;

    // ---- prologue: stage tile 0 ----
    float4 aR[4], bR[2];
    #pragma unroll
    for (int i = 0; i < 4; ++i) aR[i] = *(const float4*)pAg[i];
    #pragma unroll
    for (int i = 0; i < 2; ++i) bR[i] = *(const float4*)pBg[i];

    for (int t = 0; t < ktiles; ++t) {
        const int buf = t & 1;
        // regs -> smem (rna tf32 convert), STS.128, conflict-free
        #pragma unroll
        for (int i = 0; i < 4; ++i)
            *(uint4*)&As[buf][sA[i]] =
                make_uint4(f2tf(aR[i].x), f2tf(aR[i].y), f2tf(aR[i].z), f2tf(aR[i].w));
        #pragma unroll
        for (int i = 0; i < 2; ++i)
            *(uint4*)&Bs[buf][sB[i]] =
                make_uint4(f2tf(bR[i].x), f2tf(bR[i].y), f2tf(bR[i].z), f2tf(bR[i].w));
        __syncthreads();

        // prefetch next tile while computing this one
        if (t + 1 < ktiles) {
            const int kk = (t + 1) * BK;
            #pragma unroll
            for (int i = 0; i < 4; ++i) aR[i] = *(const float4*)(pAg[i] + kk);
            #pragma unroll
            for (int i = 0; i < 2; ++i) bR[i] = *(const float4*)(pBg[i] + kk);
        }

        // 4 k-slices of 8
        #pragma unroll
        for (int s = 0; s < 4; ++s) {
            const int c0 = 2 * s;
            uint32_t af[2][4], bf[4][2];
            #pragma unroll
            for (int mf = 0; mf < 2; ++mf) {
                af[mf][0] = As[buf][pa[mf][0] + xr[c0]];
                af[mf][1] = As[buf][pa[mf][1] + xr[c0]];
                af[mf][2] = As[buf][pa[mf][0] + xr[c0 + 1]];
                af[mf][3] = As[buf][pa[mf][1] + xr[c0 + 1]];
            }
            #pragma unroll
            for (int nf = 0; nf < 4; ++nf) {
                bf[nf][0] = Bs[buf][pb[nf] + xr[c0]];
                bf[nf][1] = Bs[buf][pb[nf] + xr[c0 + 1]];
            }
            #pragma unroll
            for (int mf = 0; mf < 2; ++mf)
                #pragma unroll
                for (int nf = 0; nf < 4; ++nf)
                    mma_tf32(acc[mf][nf], af[mf], bf[nf]);
        }
    }
}

__device__ __forceinline__ void zero_acc(float (&acc)[2][4][4]) {
    #pragma unroll
    for (int i = 0; i < 2; ++i)
        #pragma unroll
        for (int j = 0; j < 4; ++j)
            #pragma unroll
            for (int l = 0; l < 4; ++l) acc[i][j][l] = 0.0f;
}

// epilogue: write acc tile to O[ld = ldo] at (m0, n0)
__device__ __forceinline__ void store_acc(
    float* O, int ldo, int m0, int n0, const float (&acc)[2][4][4])
{
    const int lane = threadIdx.x & 31;
    const int warp = threadIdx.x >> 5;
    const int wm = (warp & 3) * 32;
    const int wn = (warp >> 2) * 32;
    #pragma unroll
    for (int mf = 0; mf < 2; ++mf)
        #pragma unroll
        for (int nf = 0; nf < 4; ++nf) {
            const int rr = m0 + wm + mf * 16 + (lane >> 2);
            const int cc = n0 + wn + nf * 8 + ((lane & 3) << 1);
            *(float2*)(O + (size_t)rr * ldo + cc)       = make_float2(acc[mf][nf][0], acc[mf][nf][1]);
            *(float2*)(O + (size_t)(rr + 8) * ldo + cc) = make_float2(acc[mf][nf][2], acc[mf][nf][3]);
        }
}

// -------------------- kernel: W transpose ([k][n] -> [n][k]) --------------
__global__ void __launch_bounds__(256) trans_w(
    const float* __restrict__ Wq, const float* __restrict__ Wk)
{
    __shared__ float t[32][33];
    const int w = blockIdx.z;
    const float* W = w ? Wk : Wq;
    float* O = g_wt + (size_t)w * DR * DE;
    const int n0 = blockIdx.x * 32, k0 = blockIdx.y * 32;
    const int tx = threadIdx.x & 31, ty = threadIdx.x >> 5;    // 32 x 8
    #pragma unroll
    for (int i = 0; i < 4; ++i)
        t[ty + 8 * i][tx] = W[(size_t)(k0 + ty + 8 * i) * DR + n0 + tx];
    __syncthreads();
    #pragma unroll
    for (int i = 0; i < 4; ++i)
        O[(size_t)(n0 + ty + 8 * i) * DE + k0 + tx] = t[tx][ty + 8 * i];
}

// -------------------- kernel 1: projections -------------------------------
// z=0: q = (x0 @ Wq + bq)/sqrt(512) ; z=1: k = x1 @ Wk + bk ; z=2: v = x2 @ Wk + bk
__global__ void __launch_bounds__(256, 2) proj_kernel(
    const float* __restrict__ x0, const float* __restrict__ x1, const float* __restrict__ x2,
    const float* __restrict__ bq, const float* __restrict__ bk)
{
    const int z = blockIdx.z;
    const float* X    = (z == 0) ? x0 : ((z == 1) ? x1 : x2);
    const float* W    = g_wt + (size_t)((z == 0) ? 0 : 1) * DR * DE;
    const float* bias = (z == 0) ? bq : bk;
    float* O          = (z == 0) ? g_q : ((z == 1) ? g_k : g_v);
    const float scale = (z == 0) ? 0.04419417382415922f : 1.0f;   // 1/sqrt(512)

    const int m0 = blockIdx.y * BM;
    const int n0 = blockIdx.x * BN;

    float acc[2][4][4];
    zero_acc(acc);
    gemm_core(X, W, DE, DE, DE / BK, m0, n0, acc);

    const int lane = threadIdx.x & 31;
    const int warp = threadIdx.x >> 5;
    const int wm = (warp & 3) * 32;
    const int wn = (warp >> 2) * 32;
    #pragma unroll
    for (int mf = 0; mf < 2; ++mf)
        #pragma unroll
        for (int nf = 0; nf < 4; ++nf) {
            const int rr = m0 + wm + mf * 16 + (lane >> 2);
            const int cc = n0 + wn + nf * 8 + ((lane & 3) << 1);
            const float b0 = bias[cc], b1 = bias[cc + 1];
            *(float2*)(O + (size_t)rr * DR + cc) =
                make_float2((acc[mf][nf][0] + b0) * scale, (acc[mf][nf][1] + b1) * scale);
            *(float2*)(O + (size_t)(rr + 8) * DR + cc) =
                make_float2((acc[mf][nf][2] + b0) * scale, (acc[mf][nf][3] + b1) * scale);
        }
}

// -------------------- kernel: V transpose ([t][d] -> [d][t]) --------------
__global__ void __launch_bounds__(256) trans_v()
{
    __shared__ float t[32][33];
    const int b = blockIdx.z;
    const float* I = g_v  + (size_t)b * N_ * DR;
    float*       O = g_vt + (size_t)b * DR * N_;
    const int t0 = blockIdx.x * 32, d0 = blockIdx.y * 32;
    const int tx = threadIdx.x & 31, ty = threadIdx.x >> 5;
    #pragma unroll
    for (int i = 0; i < 4; ++i)
        t[ty + 8 * i][tx] = I[(size_t)(t0 + ty + 8 * i) * DR + d0 + tx];
    __syncthreads();
    #pragma unroll
    for (int i = 0; i < 4; ++i)
        O[(size_t)(d0 + ty + 8 * i) * N_ + t0 + tx] = t[tx][ty + 8 * i];
}

// -------------------- kernel 2: S = Q @ K^T (causal block skip) -----------
__global__ void __launch_bounds__(256, 2) scores_kernel()
{
    const int b  = blockIdx.z;
    const int m0 = blockIdx.y * BM;
    const int n0 = blockIdx.x * BN;
    if (n0 > m0 + BM - 1) return;   // fully above diagonal: masked by softmax

    const float* Q  = g_q + (size_t)b * N_ * DR;
    const float* Km = g_k + (size_t)b * N_ * DR;
    float* S        = g_s + (size_t)b * N_ * N_;

    float acc[2][4][4];
    zero_acc(acc);
    gemm_core(Q, Km, DR, DR, DR / BK, m0, n0, acc);
    store_acc(S, N_, m0, n0, acc);
}

// -------------------- kernel 3: causal row softmax (in-place) -------------
__device__ __forceinline__ float fast_exp(float x) {
    float t = fmaxf(x * 1.4426950408889634f, -126.0f);
    float fi = floorf(t);
    float f = t - fi;
    float p = fmaf(0.00015403530393381608f, f, 0.0013333558146428443f);
    p = fmaf(p, f, 0.009618129107628477f);
    p = fmaf(p, f, 0.05550410866482158f);
    p = fmaf(p, f, 0.24022650695910072f);
    p = fmaf(p, f, 0.6931471805599453f);
    p = fmaf(p, f, 1.0f);
    return p * __int_as_float((uint32_t)((int)fi + 127) << 23);
}
__device__ __forceinline__ float brmax(float v) {
    __shared__ float sm[8];
    #pragma unroll
    for (int o = 16; o > 0; o >>= 1) v = fmaxf(v, __shfl_xor_sync(0xffffffffu, v, o));
    if ((threadIdx.x & 31) == 0) sm[threadIdx.x >> 5] = v;
    __syncthreads();
    v = sm[0];
    #pragma unroll
    for (int i = 1; i < 8; ++i) v = fmaxf(v, sm[i]);
    __syncthreads();
    return v;
}
__device__ __forceinline__ float brsum(float v) {
    __shared__ float sm2[8];
    #pragma unroll
    for (int o = 16; o > 0; o >>= 1) v += __shfl_xor_sync(0xffffffffu, v, o);
    if ((threadIdx.x & 31) == 0) sm2[threadIdx.x >> 5] = v;
    __syncthreads();
    v = sm2[0];
    #pragma unroll
    for (int i = 1; i < 8; ++i) v += sm2[i];
    __syncthreads();
    return v;
}

__global__ void __launch_bounds__(256) softmax_kernel()
{
    const int row = blockIdx.x;          // 0 .. B_*N_-1
    const int rr  = row & (N_ - 1);
    float* S = g_s + (size_t)row * N_;
    const int tid = threadIdx.x;
    const int valid = rr + 1;

    float v[8];
    float lmax = -3.402823466e38f;
    #pragma unroll
    for (int i = 0; i < 2; ++i) {
        const int c = (tid + i * 256) << 2;
        float4 f = *(const float4*)(S + c);
        v[i * 4 + 0] = (c + 0 < valid) ? f.x : -3.402823466e38f;
        v[i * 4 + 1] = (c + 1 < valid) ? f.y : -3.402823466e38f;
        v[i * 4 + 2] = (c + 2 < valid) ? f.z : -3.402823466e38f;
        v[i * 4 + 3] = (c + 3 < valid) ? f.w : -3.402823466e38f;
        lmax = fmaxf(lmax, fmaxf(fmaxf(v[i*4], v[i*4+1]), fmaxf(v[i*4+2], v[i*4+3])));
    }
    const float m = brmax(lmax);

    float lsum = 0.0f;
    #pragma unroll
    for (int i = 0; i < 8; ++i) {
        const int c = ((tid + (i >> 2) * 256) << 2) + (i & 3);
        float e = (c < valid) ? fast_exp(v[i] - m) : 0.0f;
        v[i] = e;
        lsum += e;
    }
    const float inv = 1.0f / brsum(lsum);

    #pragma unroll
    for (int i = 0; i < 2; ++i) {
        const int c = (tid + i * 256) << 2;
        *(float4*)(S + c) = make_float4(v[i*4] * inv, v[i*4+1] * inv,
                                        v[i*4+2] * inv, v[i*4+3] * inv);
    }
}

// -------------------- kernel 4: out = P @ V (causal k truncation) ---------
__global__ void __launch_bounds__(256, 2) out_kernel(float* __restrict__ out)
{
    const int b  = blockIdx.z;
    const int m0 = blockIdx.y * BM;
    const int n0 = blockIdx.x * BN;

    const float* S  = g_s  + (size_t)b * N_ * N_;
    const float* Vt = g_vt + (size_t)b * DR * N_;
    const int ktiles = (m0 + BM) / BK;   // cols > m0+127 are all zero after softmax

    float acc[2][4][4];
    zero_acc(acc);
    gemm_core(S, Vt, N_, N_, ktiles, m0, n0, acc);
    store_acc(out + (size_t)b * N_ * DR, DR, m0, n0, acc);
}

// -------------------- launch ----------------------------------------------
extern "C" void kernel_launch(void* const* d_in, const int* in_sizes, int n_in,
                              void* d_out, int out_size)
{
    (void)in_sizes; (void)n_in; (void)out_size;
    const float* x0 = (const float*)d_in[0];
    const float* x1 = (const float*)d_in[1];
    const float* x2 = (const float*)d_in[2];
    const float* bq = (const float*)d_in[4];
    const float* bk = (const float*)d_in[6];
    const float* Wq = (const float*)d_in[3];
    const float* Wk = (const float*)d_in[5];
    float* out = (float*)d_out;

    dim3 blk(256);
    trans_w<<<dim3(DR / 32, DE / 32, 2), blk>>>(Wq, Wk);
    proj_kernel<<<dim3(DR / BN, (B_ * N_) / BM, 3), blk>>>(x0, x1, x2, bq, bk);
    trans_v<<<dim3(N_ / 32, DR / 32, B_), blk>>>();
    scores_kernel<<<dim3(N_ / BN, N_ / BM, B_), blk>>>();
    softmax_kernel<<<dim3(B_ * N_), blk>>>();
    out_kernel<<<dim3(DR / BN, N_ / BM, B_), blk>>>(out);
}